// round 3
// baseline (speedup 1.0000x reference)
#include <cuda_runtime.h>
#include <cuda_fp16.h>
#include <cstdint>
#include <cstddef>

#define B_DIM   8192
#define IN_DIM  4096
#define OUT_DIM 4096

// static device scratch (runtime allocation forbidden)
__device__ __align__(16) __half g_x16[(size_t)B_DIM * IN_DIM];
__device__ __align__(16) __half g_w16[(size_t)OUT_DIM * IN_DIM];
__device__ __align__(16) float  g_sum[OUT_DIM];
__device__ __align__(16) float  g_sqs[OUT_DIM];
__device__ __align__(16) float  g_cA[OUT_DIM];
__device__ __align__(16) float  g_cB[OUT_DIM];

// ---------------- GEMM config ----------------
#define TM 128
#define TN 256
#define TK 32
#define NSTAGE 4
#define KITERS (IN_DIM / TK)       // 128
#define A_STG (TM * 64)            // 8 KB   (rows of 32 half = 64 B)
#define B_STG (TN * 64)            // 16 KB
#define STG_BYTES (A_STG + B_STG)  // 24 KB
#define GEMM_SMEM (NSTAGE * STG_BYTES)  // 96 KB

__device__ __forceinline__ uint32_t smem_u32(const void* p) {
    uint32_t r;
    asm("{ .reg .u64 t; cvta.to.shared.u64 t, %1; cvt.u32.u64 %0, t; }" : "=r"(r) : "l"(p));
    return r;
}
__device__ __forceinline__ uint32_t sw64(uint32_t o) { return o ^ ((o >> 3) & 0x30); }

#define CP_ASYNC16(dst, src) \
    asm volatile("cp.async.cg.shared.global [%0], [%1], 16;" :: "r"(dst), "l"(src) : "memory")

__device__ __forceinline__ void ldsm_x4(uint32_t* r, uint32_t addr) {
    asm volatile("ldmatrix.sync.aligned.m8n8.x4.shared.b16 {%0,%1,%2,%3}, [%4];"
                 : "=r"(r[0]), "=r"(r[1]), "=r"(r[2]), "=r"(r[3]) : "r"(addr));
}
__device__ __forceinline__ void mma16816(float* c, const uint32_t* a, const uint32_t* b) {
    asm volatile("mma.sync.aligned.m16n8k16.row.col.f32.f16.f16.f32 "
                 "{%0,%1,%2,%3}, {%4,%5,%6,%7}, {%8,%9}, {%0,%1,%2,%3};"
                 : "+f"(c[0]), "+f"(c[1]), "+f"(c[2]), "+f"(c[3])
                 : "r"(a[0]), "r"(a[1]), "r"(a[2]), "r"(a[3]), "r"(b[0]), "r"(b[1]));
}

// ---------------- conversion kernels ----------------
__global__ void cvt_x_kernel(const float* __restrict__ x) {
    size_t i = (size_t)blockIdx.x * blockDim.x + threadIdx.x;
    const float4* p = (const float4*)x;
    float4 a = p[2 * i], b = p[2 * i + 1];
    __half2 h0 = __floats2half2_rn(a.x, a.y), h1 = __floats2half2_rn(a.z, a.w);
    __half2 h2 = __floats2half2_rn(b.x, b.y), h3 = __floats2half2_rn(b.z, b.w);
    uint4 o;
    o.x = *(uint32_t*)&h0; o.y = *(uint32_t*)&h1;
    o.z = *(uint32_t*)&h2; o.w = *(uint32_t*)&h3;
    ((uint4*)g_x16)[i] = o;
}

__global__ void cvt_w_kernel(const float* __restrict__ w) {
    size_t i = (size_t)blockIdx.x * blockDim.x + threadIdx.x;
    const float4* p = (const float4*)w;
    float4 a = p[2 * i], b = p[2 * i + 1];
    float s[8] = {a.x, a.y, a.z, a.w, b.x, b.y, b.z, b.w};
    __half h[8];
#pragma unroll
    for (int k = 0; k < 8; k++) {
        float v = s[k];
        h[k] = __float2half_rn((v > 0.f) ? 1.f : ((v < 0.f) ? -1.f : 0.f));
    }
    uint4 o;
    o.x = *(uint32_t*)&h[0]; o.y = *(uint32_t*)&h[2];
    o.z = *(uint32_t*)&h[4]; o.w = *(uint32_t*)&h[6];
    ((uint4*)g_w16)[i] = o;
}

__global__ void zero_stats_kernel() {
    int i = blockIdx.x * blockDim.x + threadIdx.x;
    g_sum[i] = 0.f; g_sqs[i] = 0.f;
}

// ---------------- GEMM ----------------
__global__ void __launch_bounds__(512, 1) gemm_kernel(float* __restrict__ dout) {
    extern __shared__ char smem[];
    uint32_t sb = smem_u32(smem);
    const int tid = threadIdx.x;
    const int wid = tid >> 5, lid = tid & 31;
    const int wm = wid & 3, wn = wid >> 2;        // 4x4 warp grid
    const int m0 = blockIdx.x * TM, n0 = blockIdx.y * TN;

    const __half* gA = g_x16 + (size_t)m0 * IN_DIM;
    const __half* gB = g_w16 + (size_t)n0 * IN_DIM;

    // per-thread load coordinates
    const int arow = tid >> 2, aq = tid & 3;       // A: one 16B chunk / thread
    const uint32_t aoff = sw64((uint32_t)(arow * 64 + aq * 16));
    const int brow0 = tid >> 2, bq = tid & 3;      // B: two chunks / thread
    const uint32_t boff0 = sw64((uint32_t)(brow0 * 64 + bq * 16));
    const int brow1 = brow0 + 128;
    const uint32_t boff1 = sw64((uint32_t)(brow1 * 64 + bq * 16));

    auto load_stage = [&](int c) {
        uint32_t base = sb + (uint32_t)(c & 3) * STG_BYTES;
        const __half* ak = gA + c * TK;
        const __half* bk = gB + c * TK;
        CP_ASYNC16(base + aoff, ak + (size_t)arow * IN_DIM + aq * 8);
        uint32_t bb = base + A_STG;
        CP_ASYNC16(bb + boff0, bk + (size_t)brow0 * IN_DIM + bq * 8);
        CP_ASYNC16(bb + boff1, bk + (size_t)brow1 * IN_DIM + bq * 8);
    };

#pragma unroll
    for (int c = 0; c < 3; c++) {
        load_stage(c);
        asm volatile("cp.async.commit_group;" ::: "memory");
    }

    float acc[2][8][4];
#pragma unroll
    for (int mi = 0; mi < 2; mi++)
#pragma unroll
        for (int ni = 0; ni < 8; ni++)
#pragma unroll
            for (int q = 0; q < 4; q++) acc[mi][ni][q] = 0.f;

    // ldmatrix per-thread address components
    const uint32_t a_row_l = (uint32_t)(wm * 32 + (lid & 15));       // + mi*16
    const uint32_t a_chk_l = (uint32_t)(lid >> 4);                   // + s*2
    const uint32_t b_row_l = (uint32_t)(wn * 64 + (lid & 7) + ((lid >> 4) << 3)); // + nb*16
    const uint32_t b_chk_l = (uint32_t)((lid >> 3) & 1);             // + s*2

    for (int c = 0; c < KITERS; c++) {
        asm volatile("cp.async.wait_group 2;" ::: "memory");
        __syncthreads();
        if (c + 3 < KITERS) load_stage(c + 3);
        asm volatile("cp.async.commit_group;" ::: "memory");

        uint32_t abase = sb + (uint32_t)(c & 3) * STG_BYTES;
        uint32_t bbase = abase + A_STG;
#pragma unroll
        for (int s = 0; s < 2; s++) {
            uint32_t aF[2][4];
#pragma unroll
            for (int mi = 0; mi < 2; mi++) {
                uint32_t row = a_row_l + mi * 16;
                uint32_t chk = a_chk_l + s * 2;
                ldsm_x4(aF[mi], abase + sw64(row * 64 + chk * 16));
            }
            uint32_t bF[8][2];
#pragma unroll
            for (int nb = 0; nb < 4; nb++) {
                uint32_t q[4];
                uint32_t row = b_row_l + nb * 16;
                uint32_t chk = b_chk_l + s * 2;
                ldsm_x4(q, bbase + sw64(row * 64 + chk * 16));
                bF[2 * nb][0] = q[0]; bF[2 * nb][1] = q[1];
                bF[2 * nb + 1][0] = q[2]; bF[2 * nb + 1][1] = q[3];
            }
#pragma unroll
            for (int mi = 0; mi < 2; mi++)
#pragma unroll
                for (int ni = 0; ni < 8; ni++)
                    mma16816(acc[mi][ni], aF[mi], bF[ni]);
        }
    }

    // epilogue: direct fp32 stores
    const int trow = lid >> 2, tcol = (lid & 3) * 2;
#pragma unroll
    for (int mi = 0; mi < 2; mi++) {
#pragma unroll
        for (int ni = 0; ni < 8; ni++) {
            int row = m0 + wm * 32 + mi * 16 + trow;
            int col = n0 + wn * 64 + ni * 8 + tcol;
            float* p = dout + (size_t)row * OUT_DIM + col;
            *(float2*)p = make_float2(acc[mi][ni][0], acc[mi][ni][1]);
            *(float2*)(p + 8 * OUT_DIM) = make_float2(acc[mi][ni][2], acc[mi][ni][3]);
        }
    }
}

// ---------------- BatchNorm pieces ----------------
__global__ void stats_kernel(const float* __restrict__ o) {
    int col = blockIdx.x * 256 + threadIdx.x;
    const float* p = o + (size_t)blockIdx.y * 128 * OUT_DIM + col;
    float s = 0.f, q = 0.f;
#pragma unroll 4
    for (int r = 0; r < 128; r++) {
        float v = p[(size_t)r * OUT_DIM];
        s += v; q += v * v;
    }
    atomicAdd(&g_sum[col], s);
    atomicAdd(&g_sqs[col], q);
}

__global__ void coef_kernel(const float* __restrict__ gamma, const float* __restrict__ beta) {
    int c = blockIdx.x * 256 + threadIdx.x;
    float mu = g_sum[c] * (1.f / B_DIM);
    float var = g_sqs[c] * (1.f / B_DIM) - mu * mu;
    float a = gamma[c] * rsqrtf(var + 1e-5f);
    g_cA[c] = a;
    g_cB[c] = beta[c] - a * mu;
}

__global__ void norm_kernel(float* __restrict__ o) {
    size_t i = (size_t)blockIdx.x * blockDim.x + threadIdx.x;
    int cb = (int)((i * 4) & (OUT_DIM - 1));
    float4 v = ((float4*)o)[i];
    float4 a = *(const float4*)&g_cA[cb];
    float4 b = *(const float4*)&g_cB[cb];
    v.x = fmaf(a.x, v.x, b.x);
    v.y = fmaf(a.y, v.y, b.y);
    v.z = fmaf(a.z, v.z, b.z);
    v.w = fmaf(a.w, v.w, b.w);
    ((float4*)o)[i] = v;
}

extern "C" void kernel_launch(void* const* d_in, const int* in_sizes, int n_in,
                              void* d_out, int out_size) {
    (void)in_sizes; (void)n_in; (void)out_size;
    const float* x     = (const float*)d_in[0];
    const float* w     = (const float*)d_in[1];
    const float* gamma = (const float*)d_in[3];
    const float* beta  = (const float*)d_in[4];
    float* out = (float*)d_out;

    cudaFuncSetAttribute(gemm_kernel, cudaFuncAttributeMaxDynamicSharedMemorySize, GEMM_SMEM);

    cvt_x_kernel<<<16384, 256>>>(x);
    cvt_w_kernel<<<8192, 256>>>(w);
    zero_stats_kernel<<<16, 256>>>();
    gemm_kernel<<<dim3(B_DIM / TM, OUT_DIM / TN), 512, GEMM_SMEM>>>(out);
    stats_kernel<<<dim3(OUT_DIM / 256, B_DIM / 128), 256>>>(out);
    coef_kernel<<<16, 256>>>(gamma, beta);
    norm_kernel<<<32768, 256>>>(out);
}

// round 4
// speedup vs baseline: 1.0628x; 1.0628x over previous
#include <cuda_runtime.h>
#include <cuda_fp16.h>
#include <cstdint>
#include <cstddef>

#define B_DIM   8192
#define IN_DIM  4096
#define OUT_DIM 4096

// static device scratch (runtime allocation forbidden)
__device__ __align__(16) __half g_x16[(size_t)B_DIM * IN_DIM];
__device__ __align__(16) __half g_w16[(size_t)OUT_DIM * IN_DIM];
__device__ __align__(16) float  g_sum[OUT_DIM];
__device__ __align__(16) float  g_sqs[OUT_DIM];
__device__ __align__(16) float  g_cA[OUT_DIM];
__device__ __align__(16) float  g_cB[OUT_DIM];

// ---------------- GEMM config ----------------
#define TM 128
#define TN 256
#define TK 64
#define NSTAGE 4
#define KITERS (IN_DIM / TK)        // 64
#define A_STG (TM * 128)            // 16 KB  (row = 64 half = 128 B)
#define B_STG (TN * 128)            // 32 KB
#define STG_BYTES (A_STG + B_STG)   // 48 KB
#define GEMM_SMEM (NSTAGE * STG_BYTES)  // 192 KB

__device__ __forceinline__ uint32_t smem_u32(const void* p) {
    uint32_t r;
    asm("{ .reg .u64 t; cvta.to.shared.u64 t, %1; cvt.u32.u64 %0, t; }" : "=r"(r) : "l"(p));
    return r;
}
__device__ __forceinline__ uint32_t sw128(uint32_t o) { return o ^ ((o >> 3) & 0x70); }

#define CP_ASYNC16(dst, src) \
    asm volatile("cp.async.cg.shared.global [%0], [%1], 16;" :: "r"(dst), "l"(src) : "memory")

__device__ __forceinline__ void ldsm_x4(uint32_t* r, uint32_t addr) {
    asm volatile("ldmatrix.sync.aligned.m8n8.x4.shared.b16 {%0,%1,%2,%3}, [%4];"
                 : "=r"(r[0]), "=r"(r[1]), "=r"(r[2]), "=r"(r[3]) : "r"(addr));
}
__device__ __forceinline__ void mma16816(float* c, const uint32_t* a, const uint32_t* b) {
    asm volatile("mma.sync.aligned.m16n8k16.row.col.f32.f16.f16.f32 "
                 "{%0,%1,%2,%3}, {%4,%5,%6,%7}, {%8,%9}, {%0,%1,%2,%3};"
                 : "+f"(c[0]), "+f"(c[1]), "+f"(c[2]), "+f"(c[3])
                 : "r"(a[0]), "r"(a[1]), "r"(a[2]), "r"(a[3]), "r"(b[0]), "r"(b[1]));
}

// ---------------- conversion kernels ----------------
__global__ void cvt_x_kernel(const float* __restrict__ x) {
    size_t i = (size_t)blockIdx.x * blockDim.x + threadIdx.x;
    const float4* p = (const float4*)x;
    float4 a = p[2 * i], b = p[2 * i + 1];
    __half2 h0 = __floats2half2_rn(a.x, a.y), h1 = __floats2half2_rn(a.z, a.w);
    __half2 h2 = __floats2half2_rn(b.x, b.y), h3 = __floats2half2_rn(b.z, b.w);
    uint4 o;
    o.x = *(uint32_t*)&h0; o.y = *(uint32_t*)&h1;
    o.z = *(uint32_t*)&h2; o.w = *(uint32_t*)&h3;
    ((uint4*)g_x16)[i] = o;
}

__global__ void cvt_w_kernel(const float* __restrict__ w) {
    size_t i = (size_t)blockIdx.x * blockDim.x + threadIdx.x;
    const float4* p = (const float4*)w;
    float4 a = p[2 * i], b = p[2 * i + 1];
    float s[8] = {a.x, a.y, a.z, a.w, b.x, b.y, b.z, b.w};
    __half h[8];
#pragma unroll
    for (int k = 0; k < 8; k++) {
        float v = s[k];
        h[k] = __float2half_rn((v > 0.f) ? 1.f : ((v < 0.f) ? -1.f : 0.f));
    }
    uint4 o;
    o.x = *(uint32_t*)&h[0]; o.y = *(uint32_t*)&h[2];
    o.z = *(uint32_t*)&h[4]; o.w = *(uint32_t*)&h[6];
    ((uint4*)g_w16)[i] = o;
}

__global__ void zero_stats_kernel() {
    int i = blockIdx.x * blockDim.x + threadIdx.x;
    g_sum[i] = 0.f; g_sqs[i] = 0.f;
}

// ---------------- GEMM (8 warps, 64x64 warp tiles, fused stats) ----------------
__global__ void __launch_bounds__(256, 1) gemm_kernel(float* __restrict__ dout) {
    extern __shared__ char smem[];
    uint32_t sb = smem_u32(smem);
    const int tid = threadIdx.x;
    const int wid = tid >> 5, lid = tid & 31;
    const int wm = wid >> 2, wn = wid & 3;        // 2 x 4 warp grid
    const int m0 = blockIdx.x * TM, n0 = blockIdx.y * TN;

    const __half* gA = g_x16 + (size_t)m0 * IN_DIM;
    const __half* gB = g_w16 + (size_t)n0 * IN_DIM;

    // cp.async per-thread coordinates: 8 chunks/row of 128B
    const int ldr = tid >> 3, ldq = tid & 7;

    auto load_stage = [&](int c) {
        uint32_t base = sb + (uint32_t)(c & 3) * STG_BYTES;
        const __half* ak = gA + c * TK;
        const __half* bk = gB + c * TK;
#pragma unroll
        for (int j = 0; j < 4; j++) {              // A: 128 rows
            int r = ldr + j * 32;
            CP_ASYNC16(base + sw128((uint32_t)(r * 128 + ldq * 16)),
                       ak + (size_t)r * IN_DIM + ldq * 8);
        }
        uint32_t bb = base + A_STG;
#pragma unroll
        for (int j = 0; j < 8; j++) {              // B: 256 rows
            int r = ldr + j * 32;
            CP_ASYNC16(bb + sw128((uint32_t)(r * 128 + ldq * 16)),
                       bk + (size_t)r * IN_DIM + ldq * 8);
        }
    };

#pragma unroll
    for (int c = 0; c < 3; c++) {
        load_stage(c);
        asm volatile("cp.async.commit_group;" ::: "memory");
    }

    float acc[4][8][4];
#pragma unroll
    for (int mi = 0; mi < 4; mi++)
#pragma unroll
        for (int ni = 0; ni < 8; ni++)
#pragma unroll
            for (int q = 0; q < 4; q++) acc[mi][ni][q] = 0.f;

    // ldmatrix per-thread address components
    const uint32_t a_row_l = (uint32_t)(wm * 64 + (lid & 15));
    const uint32_t a_col_l = (uint32_t)((lid >> 4) * 16);
    const uint32_t b_row_l = (uint32_t)(wn * 64 + (lid & 7) + ((lid >> 4) << 3));
    const uint32_t b_col_l = (uint32_t)(((lid >> 3) & 1) * 16);

    uint32_t aB[2][4][4], bB[2][4][4];

    for (int c = 0; c < KITERS; c++) {
        asm volatile("cp.async.wait_group 2;" ::: "memory");
        __syncthreads();
        if (c + 3 < KITERS) load_stage(c + 3);
        asm volatile("cp.async.commit_group;" ::: "memory");

        uint32_t abase = sb + (uint32_t)(c & 3) * STG_BYTES;
        uint32_t bbase = abase + A_STG;

#define LOADFR(buf, ks) do {                                                      \
    _Pragma("unroll")                                                             \
    for (int mi = 0; mi < 4; mi++)                                                \
        ldsm_x4(aB[buf][mi], abase + sw128((a_row_l + mi * 16) * 128 + a_col_l + (ks) * 32)); \
    _Pragma("unroll")                                                             \
    for (int nb = 0; nb < 4; nb++)                                                \
        ldsm_x4(bB[buf][nb], bbase + sw128((b_row_l + nb * 16) * 128 + b_col_l + (ks) * 32)); \
} while (0)

        LOADFR(0, 0);
#pragma unroll
        for (int s = 0; s < 4; s++) {
            if (s < 3) LOADFR((s + 1) & 1, s + 1);
            const int b = s & 1;
#pragma unroll
            for (int mi = 0; mi < 4; mi++)
#pragma unroll
                for (int nb = 0; nb < 4; nb++) {
                    mma16816(acc[mi][2 * nb],     aB[b][mi], &bB[b][nb][0]);
                    mma16816(acc[mi][2 * nb + 1], aB[b][mi], &bB[b][nb][2]);
                }
        }
#undef LOADFR
    }

    // ---- epilogue: store fp32 + fused column stats ----
    const int trow = lid >> 2, tcol = (lid & 3) * 2;
#pragma unroll
    for (int mi = 0; mi < 4; mi++) {
#pragma unroll
        for (int ni = 0; ni < 8; ni++) {
            int row = m0 + wm * 64 + mi * 16 + trow;
            int col = n0 + wn * 64 + ni * 8 + tcol;
            float* p = dout + (size_t)row * OUT_DIM + col;
            *(float2*)p = make_float2(acc[mi][ni][0], acc[mi][ni][1]);
            *(float2*)(p + 8 * OUT_DIM) = make_float2(acc[mi][ni][2], acc[mi][ni][3]);
        }
    }
#pragma unroll
    for (int ni = 0; ni < 8; ni++) {
        float s0 = 0.f, s1 = 0.f, q0 = 0.f, q1 = 0.f;
#pragma unroll
        for (int mi = 0; mi < 4; mi++) {
            float v0 = acc[mi][ni][0], v1 = acc[mi][ni][1];
            float v2 = acc[mi][ni][2], v3 = acc[mi][ni][3];
            s0 += v0 + v2; s1 += v1 + v3;
            q0 += v0 * v0 + v2 * v2; q1 += v1 * v1 + v3 * v3;
        }
#pragma unroll
        for (int off = 4; off < 32; off <<= 1) {
            s0 += __shfl_xor_sync(0xffffffffu, s0, off);
            s1 += __shfl_xor_sync(0xffffffffu, s1, off);
            q0 += __shfl_xor_sync(0xffffffffu, q0, off);
            q1 += __shfl_xor_sync(0xffffffffu, q1, off);
        }
        if (trow == 0) {
            int col = n0 + wn * 64 + ni * 8 + tcol;
            atomicAdd(&g_sum[col], s0);
            atomicAdd(&g_sum[col + 1], s1);
            atomicAdd(&g_sqs[col], q0);
            atomicAdd(&g_sqs[col + 1], q1);
        }
    }
}

// ---------------- BatchNorm tail ----------------
__global__ void coef_kernel(const float* __restrict__ gamma, const float* __restrict__ beta) {
    int c = blockIdx.x * 256 + threadIdx.x;
    float mu = g_sum[c] * (1.f / B_DIM);
    float var = g_sqs[c] * (1.f / B_DIM) - mu * mu;
    float a = gamma[c] * rsqrtf(var + 1e-5f);
    g_cA[c] = a;
    g_cB[c] = beta[c] - a * mu;
}

__global__ void norm_kernel(float* __restrict__ o) {
    size_t i = (size_t)blockIdx.x * blockDim.x + threadIdx.x;
    int cb = (int)((i * 4) & (OUT_DIM - 1));
    float4 v = ((float4*)o)[i];
    float4 a = *(const float4*)&g_cA[cb];
    float4 b = *(const float4*)&g_cB[cb];
    v.x = fmaf(a.x, v.x, b.x);
    v.y = fmaf(a.y, v.y, b.y);
    v.z = fmaf(a.z, v.z, b.z);
    v.w = fmaf(a.w, v.w, b.w);
    ((float4*)o)[i] = v;
}

extern "C" void kernel_launch(void* const* d_in, const int* in_sizes, int n_in,
                              void* d_out, int out_size) {
    (void)in_sizes; (void)n_in; (void)out_size;
    const float* x     = (const float*)d_in[0];
    const float* w     = (const float*)d_in[1];
    const float* gamma = (const float*)d_in[3];
    const float* beta  = (const float*)d_in[4];
    float* out = (float*)d_out;

    cudaFuncSetAttribute(gemm_kernel, cudaFuncAttributeMaxDynamicSharedMemorySize, GEMM_SMEM);

    cvt_x_kernel<<<16384, 256>>>(x);
    cvt_w_kernel<<<8192, 256>>>(w);
    zero_stats_kernel<<<16, 256>>>();
    gemm_kernel<<<dim3(B_DIM / TM, OUT_DIM / TN), 256, GEMM_SMEM>>>(out);
    coef_kernel<<<16, 256>>>(gamma, beta);
    norm_kernel<<<32768, 256>>>(out);
}

// round 5
// speedup vs baseline: 1.1657x; 1.0968x over previous
#include <cuda_runtime.h>
#include <cuda_fp16.h>
#include <cstdint>
#include <cstddef>

#define B_DIM   8192
#define IN_DIM  4096
#define OUT_DIM 4096

// static device scratch (runtime allocation forbidden)
__device__ __align__(16) __half g_x16[(size_t)B_DIM * IN_DIM];
__device__ __align__(16) __half g_w16[(size_t)OUT_DIM * IN_DIM];
__device__ __align__(16) __half g_o16[(size_t)B_DIM * OUT_DIM];
__device__ __align__(16) float  g_sum[OUT_DIM];
__device__ __align__(16) float  g_sqs[OUT_DIM];
__device__ __align__(16) float  g_cA[OUT_DIM];
__device__ __align__(16) float  g_cB[OUT_DIM];

// ---------------- GEMM config ----------------
#define TM 128
#define TN 256
#define TK 64
#define NSTAGE 4
#define KITERS (IN_DIM / TK)        // 64
#define A_STG (TM * 128)            // 16 KB
#define B_STG (TN * 128)            // 32 KB
#define STG_BYTES (A_STG + B_STG)   // 48 KB
#define GEMM_SMEM (NSTAGE * STG_BYTES)  // 192 KB

__device__ __forceinline__ uint32_t smem_u32(const void* p) {
    uint32_t r;
    asm("{ .reg .u64 t; cvta.to.shared.u64 t, %1; cvt.u32.u64 %0, t; }" : "=r"(r) : "l"(p));
    return r;
}
__device__ __forceinline__ uint32_t sw128(uint32_t o) { return o ^ ((o >> 3) & 0x70); }

#define CP_ASYNC16(dst, src) \
    asm volatile("cp.async.cg.shared.global [%0], [%1], 16;" :: "r"(dst), "l"(src) : "memory")

__device__ __forceinline__ void ldsm_x4(uint32_t* r, uint32_t addr) {
    asm volatile("ldmatrix.sync.aligned.m8n8.x4.shared.b16 {%0,%1,%2,%3}, [%4];"
                 : "=r"(r[0]), "=r"(r[1]), "=r"(r[2]), "=r"(r[3]) : "r"(addr));
}
__device__ __forceinline__ void mma16816(float* c, const uint32_t* a, const uint32_t* b) {
    asm volatile("mma.sync.aligned.m16n8k16.row.col.f32.f16.f16.f32 "
                 "{%0,%1,%2,%3}, {%4,%5,%6,%7}, {%8,%9}, {%0,%1,%2,%3};"
                 : "+f"(c[0]), "+f"(c[1]), "+f"(c[2]), "+f"(c[3])
                 : "r"(a[0]), "r"(a[1]), "r"(a[2]), "r"(a[3]), "r"(b[0]), "r"(b[1]));
}

// ---------------- conversion kernels ----------------
__global__ void cvt_x_kernel(const float* __restrict__ x) {
    size_t i = (size_t)blockIdx.x * blockDim.x + threadIdx.x;
    const float4* p = (const float4*)x;
    float4 a = p[2 * i], b = p[2 * i + 1];
    __half2 h0 = __floats2half2_rn(a.x, a.y), h1 = __floats2half2_rn(a.z, a.w);
    __half2 h2 = __floats2half2_rn(b.x, b.y), h3 = __floats2half2_rn(b.z, b.w);
    uint4 o;
    o.x = *(uint32_t*)&h0; o.y = *(uint32_t*)&h1;
    o.z = *(uint32_t*)&h2; o.w = *(uint32_t*)&h3;
    ((uint4*)g_x16)[i] = o;
}

__global__ void cvt_w_kernel(const float* __restrict__ w) {
    size_t i = (size_t)blockIdx.x * blockDim.x + threadIdx.x;
    const float4* p = (const float4*)w;
    float4 a = p[2 * i], b = p[2 * i + 1];
    float s[8] = {a.x, a.y, a.z, a.w, b.x, b.y, b.z, b.w};
    __half h[8];
#pragma unroll
    for (int k = 0; k < 8; k++) {
        float v = s[k];
        h[k] = __float2half_rn((v > 0.f) ? 1.f : ((v < 0.f) ? -1.f : 0.f));
    }
    uint4 o;
    o.x = *(uint32_t*)&h[0]; o.y = *(uint32_t*)&h[2];
    o.z = *(uint32_t*)&h[4]; o.w = *(uint32_t*)&h[6];
    ((uint4*)g_w16)[i] = o;
}

__global__ void zero_stats_kernel() {
    int i = blockIdx.x * blockDim.x + threadIdx.x;
    g_sum[i] = 0.f; g_sqs[i] = 0.f;
}

// ---------------- GEMM (8 warps, 64x64 warp tiles, spread cp.async, fused stats) ----
__global__ void __launch_bounds__(256, 1) gemm_kernel() {
    extern __shared__ char smem[];
    uint32_t sb = smem_u32(smem);
    const int tid = threadIdx.x;
    const int wid = tid >> 5, lid = tid & 31;
    const int wm = wid >> 2, wn = wid & 3;        // 2 x 4 warp grid
    const int m0 = blockIdx.x * TM, n0 = blockIdx.y * TN;

    const __half* gA = g_x16 + (size_t)m0 * IN_DIM;
    const __half* gB = g_w16 + (size_t)n0 * IN_DIM;

    const int ldr = tid >> 3, ldq = tid & 7;

    // flat 12-chunk list per thread: j<4 -> A rows, j>=4 -> B rows
    auto issue_chunk = [&](int c, int j) {
        uint32_t base = sb + (uint32_t)(c & 3) * STG_BYTES;
        if (j < 4) {
            int r = ldr + j * 32;
            CP_ASYNC16(base + sw128((uint32_t)(r * 128 + ldq * 16)),
                       gA + (size_t)c * TK + (size_t)r * IN_DIM + ldq * 8);
        } else {
            int r = ldr + (j - 4) * 32;
            CP_ASYNC16(base + A_STG + sw128((uint32_t)(r * 128 + ldq * 16)),
                       gB + (size_t)c * TK + (size_t)r * IN_DIM + ldq * 8);
        }
    };

#pragma unroll
    for (int c = 0; c < 3; c++) {
#pragma unroll
        for (int j = 0; j < 12; j++) issue_chunk(c, j);
        asm volatile("cp.async.commit_group;" ::: "memory");
    }

    float acc[4][8][4];
#pragma unroll
    for (int mi = 0; mi < 4; mi++)
#pragma unroll
        for (int ni = 0; ni < 8; ni++)
#pragma unroll
            for (int q = 0; q < 4; q++) acc[mi][ni][q] = 0.f;

    const uint32_t a_row_l = (uint32_t)(wm * 64 + (lid & 15));
    const uint32_t a_col_l = (uint32_t)((lid >> 4) * 16);
    const uint32_t b_row_l = (uint32_t)(wn * 64 + (lid & 7) + ((lid >> 4) << 3));
    const uint32_t b_col_l = (uint32_t)(((lid >> 3) & 1) * 16);

    uint32_t aB[2][4][4], bB[2][4][4];

    for (int c = 0; c < KITERS; c++) {
        asm volatile("cp.async.wait_group 2;" ::: "memory");
        __syncthreads();
        const bool pf = (c + 3 < KITERS);

        uint32_t abase = sb + (uint32_t)(c & 3) * STG_BYTES;
        uint32_t bbase = abase + A_STG;

#define LOADFR(buf, ks) do {                                                      \
    _Pragma("unroll")                                                             \
    for (int mi = 0; mi < 4; mi++)                                                \
        ldsm_x4(aB[buf][mi], abase + sw128((a_row_l + mi * 16) * 128 + a_col_l + (ks) * 32)); \
    _Pragma("unroll")                                                             \
    for (int nb = 0; nb < 4; nb++)                                                \
        ldsm_x4(bB[buf][nb], bbase + sw128((b_row_l + nb * 16) * 128 + b_col_l + (ks) * 32)); \
} while (0)

        LOADFR(0, 0);
#pragma unroll
        for (int s = 0; s < 4; s++) {
            if (s < 3) LOADFR((s + 1) & 1, s + 1);
            if (pf) {                               // 3 cp.async per sub-step
#pragma unroll
                for (int j = 0; j < 3; j++) issue_chunk(c + 3, s * 3 + j);
            }
            const int b = s & 1;
#pragma unroll
            for (int mi = 0; mi < 4; mi++)
#pragma unroll
                for (int nb = 0; nb < 4; nb++) {
                    mma16816(acc[mi][2 * nb],     aB[b][mi], &bB[b][nb][0]);
                    mma16816(acc[mi][2 * nb + 1], aB[b][mi], &bB[b][nb][2]);
                }
        }
#undef LOADFR
        asm volatile("cp.async.commit_group;" ::: "memory");
    }

    // ---- epilogue: fp16 store + fused column stats (fp32) ----
    const int trow = lid >> 2, tcol = (lid & 3) * 2;
#pragma unroll
    for (int mi = 0; mi < 4; mi++) {
#pragma unroll
        for (int ni = 0; ni < 8; ni++) {
            int row = m0 + wm * 64 + mi * 16 + trow;
            int col = n0 + wn * 64 + ni * 8 + tcol;
            __half* p = g_o16 + (size_t)row * OUT_DIM + col;
            *(__half2*)p = __floats2half2_rn(acc[mi][ni][0], acc[mi][ni][1]);
            *(__half2*)(p + 8 * OUT_DIM) = __floats2half2_rn(acc[mi][ni][2], acc[mi][ni][3]);
        }
    }
#pragma unroll
    for (int ni = 0; ni < 8; ni++) {
        float s0 = 0.f, s1 = 0.f, q0 = 0.f, q1 = 0.f;
#pragma unroll
        for (int mi = 0; mi < 4; mi++) {
            float v0 = acc[mi][ni][0], v1 = acc[mi][ni][1];
            float v2 = acc[mi][ni][2], v3 = acc[mi][ni][3];
            s0 += v0 + v2; s1 += v1 + v3;
            q0 += v0 * v0 + v2 * v2; q1 += v1 * v1 + v3 * v3;
        }
#pragma unroll
        for (int off = 4; off < 32; off <<= 1) {
            s0 += __shfl_xor_sync(0xffffffffu, s0, off);
            s1 += __shfl_xor_sync(0xffffffffu, s1, off);
            q0 += __shfl_xor_sync(0xffffffffu, q0, off);
            q1 += __shfl_xor_sync(0xffffffffu, q1, off);
        }
        if (trow == 0) {
            int col = n0 + wn * 64 + ni * 8 + tcol;
            atomicAdd(&g_sum[col], s0);
            atomicAdd(&g_sum[col + 1], s1);
            atomicAdd(&g_sqs[col], q0);
            atomicAdd(&g_sqs[col + 1], q1);
        }
    }
}

// ---------------- BatchNorm tail ----------------
__global__ void coef_kernel(const float* __restrict__ gamma, const float* __restrict__ beta) {
    int c = blockIdx.x * 256 + threadIdx.x;
    float mu = g_sum[c] * (1.f / B_DIM);
    float var = g_sqs[c] * (1.f / B_DIM) - mu * mu;
    float a = gamma[c] * rsqrtf(var + 1e-5f);
    g_cA[c] = a;
    g_cB[c] = beta[c] - a * mu;
}

__global__ void norm_kernel(float* __restrict__ out) {
    size_t i = (size_t)blockIdx.x * blockDim.x + threadIdx.x;  // one 8-half group
    int col = (int)((i * 8) & (OUT_DIM - 1));
    uint4 v = ((const uint4*)g_o16)[i];
    float4 a0 = *(const float4*)&g_cA[col];
    float4 a1 = *(const float4*)&g_cA[col + 4];
    float4 b0 = *(const float4*)&g_cB[col];
    float4 b1 = *(const float4*)&g_cB[col + 4];
    float2 f0 = __half22float2(*(__half2*)&v.x);
    float2 f1 = __half22float2(*(__half2*)&v.y);
    float2 f2 = __half22float2(*(__half2*)&v.z);
    float2 f3 = __half22float2(*(__half2*)&v.w);
    float4 r0, r1;
    r0.x = fmaf(a0.x, f0.x, b0.x); r0.y = fmaf(a0.y, f0.y, b0.y);
    r0.z = fmaf(a0.z, f1.x, b0.z); r0.w = fmaf(a0.w, f1.y, b0.w);
    r1.x = fmaf(a1.x, f2.x, b1.x); r1.y = fmaf(a1.y, f2.y, b1.y);
    r1.z = fmaf(a1.z, f3.x, b1.z); r1.w = fmaf(a1.w, f3.y, b1.w);
    ((float4*)out)[2 * i]     = r0;
    ((float4*)out)[2 * i + 1] = r1;
}

extern "C" void kernel_launch(void* const* d_in, const int* in_sizes, int n_in,
                              void* d_out, int out_size) {
    (void)in_sizes; (void)n_in; (void)out_size;
    const float* x     = (const float*)d_in[0];
    const float* w     = (const float*)d_in[1];
    const float* gamma = (const float*)d_in[3];
    const float* beta  = (const float*)d_in[4];
    float* out = (float*)d_out;

    cudaFuncSetAttribute(gemm_kernel, cudaFuncAttributeMaxDynamicSharedMemorySize, GEMM_SMEM);

    cvt_x_kernel<<<16384, 256>>>(x);
    cvt_w_kernel<<<8192, 256>>>(w);
    zero_stats_kernel<<<16, 256>>>();
    gemm_kernel<<<dim3(B_DIM / TM, OUT_DIM / TN), 256, GEMM_SMEM>>>();
    coef_kernel<<<16, 256>>>(gamma, beta);
    norm_kernel<<<16384, 256>>>(out);
}

// round 7
// speedup vs baseline: 1.1891x; 1.0201x over previous
#include <cuda_runtime.h>
#include <cuda_fp16.h>
#include <cstdint>
#include <cstddef>

#define B_DIM   8192
#define IN_DIM  4096
#define OUT_DIM 4096

// static device scratch (runtime allocation forbidden)
__device__ __align__(16) __half g_x16[(size_t)B_DIM * IN_DIM];
__device__ __align__(16) __half g_w16[(size_t)OUT_DIM * IN_DIM];
__device__ __align__(16) __half g_o16[(size_t)B_DIM * OUT_DIM];
__device__ __align__(16) float  g_sum[OUT_DIM];
__device__ __align__(16) float  g_sqs[OUT_DIM];
__device__ __align__(16) float  g_cA[OUT_DIM];
__device__ __align__(16) float  g_cB[OUT_DIM];

// ---------------- GEMM config ----------------
#define TM 128
#define TN 256
#define TK 64
#define NSTAGE 4
#define KITERS (IN_DIM / TK)        // 64
#define A_STG (TM * 128)            // 16 KB
#define B_STG (TN * 128)            // 32 KB
#define STG_BYTES (A_STG + B_STG)   // 48 KB
#define GEMM_SMEM (NSTAGE * STG_BYTES)  // 192 KB

__device__ __forceinline__ uint32_t smem_u32(const void* p) {
    uint32_t r;
    asm("{ .reg .u64 t; cvta.to.shared.u64 t, %1; cvt.u32.u64 %0, t; }" : "=r"(r) : "l"(p));
    return r;
}
__device__ __forceinline__ uint32_t sw128(uint32_t o) { return o ^ ((o >> 3) & 0x70); }

#define CP_ASYNC16(dst, src) \
    asm volatile("cp.async.cg.shared.global [%0], [%1], 16;" :: "r"(dst), "l"(src) : "memory")

__device__ __forceinline__ void ldsm_x4(uint32_t* r, uint32_t addr) {
    asm volatile("ldmatrix.sync.aligned.m8n8.x4.shared.b16 {%0,%1,%2,%3}, [%4];"
                 : "=r"(r[0]), "=r"(r[1]), "=r"(r[2]), "=r"(r[3]) : "r"(addr));
}
__device__ __forceinline__ void mma16816(float* c, const uint32_t* a, const uint32_t* b) {
    asm volatile("mma.sync.aligned.m16n8k16.row.col.f32.f16.f16.f32 "
                 "{%0,%1,%2,%3}, {%4,%5,%6,%7}, {%8,%9}, {%0,%1,%2,%3};"
                 : "+f"(c[0]), "+f"(c[1]), "+f"(c[2]), "+f"(c[3])
                 : "r"(a[0]), "r"(a[1]), "r"(a[2]), "r"(a[3]), "r"(b[0]), "r"(b[1]));
}

// ---------------- conversion kernels ----------------
__global__ void cvt_x_kernel(const float* __restrict__ x) {
    size_t i = (size_t)blockIdx.x * blockDim.x + threadIdx.x;
    const float4* p = (const float4*)x;
    float4 a = p[2 * i], b = p[2 * i + 1];
    __half2 h0 = __floats2half2_rn(a.x, a.y), h1 = __floats2half2_rn(a.z, a.w);
    __half2 h2 = __floats2half2_rn(b.x, b.y), h3 = __floats2half2_rn(b.z, b.w);
    uint4 o;
    o.x = *(uint32_t*)&h0; o.y = *(uint32_t*)&h1;
    o.z = *(uint32_t*)&h2; o.w = *(uint32_t*)&h3;
    ((uint4*)g_x16)[i] = o;
}

__global__ void cvt_w_kernel(const float* __restrict__ w) {
    size_t i = (size_t)blockIdx.x * blockDim.x + threadIdx.x;
    if (i < OUT_DIM) { g_sum[i] = 0.f; g_sqs[i] = 0.f; }   // fused stats zeroing
    const float4* p = (const float4*)w;
    float4 a = p[2 * i], b = p[2 * i + 1];
    float s[8] = {a.x, a.y, a.z, a.w, b.x, b.y, b.z, b.w};
    __half h[8];
#pragma unroll
    for (int k = 0; k < 8; k++) {
        float v = s[k];
        h[k] = __float2half_rn((v > 0.f) ? 1.f : ((v < 0.f) ? -1.f : 0.f));
    }
    uint4 o;
    o.x = *(uint32_t*)&h[0]; o.y = *(uint32_t*)&h[2];
    o.z = *(uint32_t*)&h[4]; o.w = *(uint32_t*)&h[6];
    ((uint4*)g_w16)[i] = o;
}

// ---------------- GEMM (8 warps, 64x64 warp tiles, mma-first substeps) -------
__global__ void __launch_bounds__(256, 1) gemm_kernel() {
    extern __shared__ char smem[];
    uint32_t sb = smem_u32(smem);
    const int tid = threadIdx.x;
    const int wid = tid >> 5, lid = tid & 31;
    const int wm = wid >> 2, wn = wid & 3;        // 2 x 4 warp grid
    const int m0 = blockIdx.x * TM, n0 = blockIdx.y * TN;

    const __half* gA = g_x16 + (size_t)m0 * IN_DIM;
    const __half* gB = g_w16 + (size_t)n0 * IN_DIM;

    const int ldr = tid >> 3, ldq = tid & 7;

    // flat 12-chunk list per thread: j<4 -> A rows, j>=4 -> B rows
    auto issue_chunk = [&](int c, int j) {
        uint32_t base = sb + (uint32_t)(c & 3) * STG_BYTES;
        if (j < 4) {
            int r = ldr + j * 32;
            CP_ASYNC16(base + sw128((uint32_t)(r * 128 + ldq * 16)),
                       gA + (size_t)c * TK + (size_t)r * IN_DIM + ldq * 8);
        } else {
            int r = ldr + (j - 4) * 32;
            CP_ASYNC16(base + A_STG + sw128((uint32_t)(r * 128 + ldq * 16)),
                       gB + (size_t)c * TK + (size_t)r * IN_DIM + ldq * 8);
        }
    };

#pragma unroll
    for (int c = 0; c < 3; c++) {
#pragma unroll
        for (int j = 0; j < 12; j++) issue_chunk(c, j);
        asm volatile("cp.async.commit_group;" ::: "memory");
    }

    float acc[4][8][4];
#pragma unroll
    for (int mi = 0; mi < 4; mi++)
#pragma unroll
        for (int ni = 0; ni < 8; ni++)
#pragma unroll
            for (int q = 0; q < 4; q++) acc[mi][ni][q] = 0.f;

    const uint32_t a_row_l = (uint32_t)(wm * 64 + (lid & 15));
    const uint32_t a_col_l = (uint32_t)((lid >> 4) * 16);
    const uint32_t b_row_l = (uint32_t)(wn * 64 + (lid & 7) + ((lid >> 4) << 3));
    const uint32_t b_col_l = (uint32_t)(((lid >> 3) & 1) * 16);

    uint32_t aB[2][4][4], bB[2][4][4];

#define LOADFR(buf, ks) do {                                                      \
    _Pragma("unroll")                                                             \
    for (int mi = 0; mi < 4; mi++)                                                \
        ldsm_x4(aB[buf][mi], abase + sw128((a_row_l + mi * 16) * 128 + a_col_l + (ks) * 32)); \
    _Pragma("unroll")                                                             \
    for (int nb = 0; nb < 4; nb++)                                                \
        ldsm_x4(bB[buf][nb], bbase + sw128((b_row_l + nb * 16) * 128 + b_col_l + (ks) * 32)); \
} while (0)

#define MMABLK(buf) do {                                                          \
    _Pragma("unroll")                                                             \
    for (int mi = 0; mi < 4; mi++)                                                \
        _Pragma("unroll")                                                         \
        for (int nb = 0; nb < 4; nb++) {                                          \
            mma16816(acc[mi][2 * nb],     aB[buf][mi], &bB[buf][nb][0]);          \
            mma16816(acc[mi][2 * nb + 1], aB[buf][mi], &bB[buf][nb][2]);          \
        }                                                                         \
} while (0)

#define ISSUE3(j0) do {                                                           \
    if (pf) { issue_chunk(c + 3, (j0)); issue_chunk(c + 3, (j0) + 1); issue_chunk(c + 3, (j0) + 2); } \
} while (0)

    for (int c = 0; c < KITERS; c++) {
        uint32_t abase = sb + (uint32_t)(c & 3) * STG_BYTES;
        uint32_t bbase = abase + A_STG;
        const bool pf = (c + 3 < KITERS);

        asm volatile("cp.async.wait_group 2;" ::: "memory");
        __syncthreads();   // REQUIRED before reading other threads' cp.async data

        LOADFR(0, 0);
        LOADFR(1, 1); MMABLK(0); ISSUE3(0);
        LOADFR(0, 2); MMABLK(1); ISSUE3(3);
        LOADFR(1, 3); MMABLK(0); ISSUE3(6);
        MMABLK(1);               ISSUE3(9);
        asm volatile("cp.async.commit_group;" ::: "memory");
    }
#undef LOADFR
#undef MMABLK
#undef ISSUE3

    // ---- epilogue: fp16 store + fused column stats (fp32) ----
    const int trow = lid >> 2, tcol = (lid & 3) * 2;
#pragma unroll
    for (int mi = 0; mi < 4; mi++) {
#pragma unroll
        for (int ni = 0; ni < 8; ni++) {
            int row = m0 + wm * 64 + mi * 16 + trow;
            int col = n0 + wn * 64 + ni * 8 + tcol;
            __half* p = g_o16 + (size_t)row * OUT_DIM + col;
            *(__half2*)p = __floats2half2_rn(acc[mi][ni][0], acc[mi][ni][1]);
            *(__half2*)(p + 8 * OUT_DIM) = __floats2half2_rn(acc[mi][ni][2], acc[mi][ni][3]);
        }
    }
#pragma unroll
    for (int ni = 0; ni < 8; ni++) {
        float s0 = 0.f, s1 = 0.f, q0 = 0.f, q1 = 0.f;
#pragma unroll
        for (int mi = 0; mi < 4; mi++) {
            float v0 = acc[mi][ni][0], v1 = acc[mi][ni][1];
            float v2 = acc[mi][ni][2], v3 = acc[mi][ni][3];
            s0 += v0 + v2; s1 += v1 + v3;
            q0 += v0 * v0 + v2 * v2; q1 += v1 * v1 + v3 * v3;
        }
#pragma unroll
        for (int off = 4; off < 32; off <<= 1) {
            s0 += __shfl_xor_sync(0xffffffffu, s0, off);
            s1 += __shfl_xor_sync(0xffffffffu, s1, off);
            q0 += __shfl_xor_sync(0xffffffffu, q0, off);
            q1 += __shfl_xor_sync(0xffffffffu, q1, off);
        }
        if (trow == 0) {
            int col = n0 + wn * 64 + ni * 8 + tcol;
            atomicAdd(&g_sum[col], s0);
            atomicAdd(&g_sum[col + 1], s1);
            atomicAdd(&g_sqs[col], q0);
            atomicAdd(&g_sqs[col + 1], q1);
        }
    }
}

// ---------------- BatchNorm tail ----------------
__global__ void coef_kernel(const float* __restrict__ gamma, const float* __restrict__ beta) {
    int c = blockIdx.x * 256 + threadIdx.x;
    float mu = g_sum[c] * (1.f / B_DIM);
    float var = g_sqs[c] * (1.f / B_DIM) - mu * mu;
    float a = gamma[c] * rsqrtf(var + 1e-5f);
    g_cA[c] = a;
    g_cB[c] = beta[c] - a * mu;
}

__global__ void norm_kernel(float* __restrict__ out) {
    size_t i = (size_t)blockIdx.x * blockDim.x + threadIdx.x;  // one 8-half group
    int col = (int)((i * 8) & (OUT_DIM - 1));
    uint4 v = ((const uint4*)g_o16)[i];
    float4 a0 = *(const float4*)&g_cA[col];
    float4 a1 = *(const float4*)&g_cA[col + 4];
    float4 b0 = *(const float4*)&g_cB[col];
    float4 b1 = *(const float4*)&g_cB[col + 4];
    float2 f0 = __half22float2(*(__half2*)&v.x);
    float2 f1 = __half22float2(*(__half2*)&v.y);
    float2 f2 = __half22float2(*(__half2*)&v.z);
    float2 f3 = __half22float2(*(__half2*)&v.w);
    float4 r0, r1;
    r0.x = fmaf(a0.x, f0.x, b0.x); r0.y = fmaf(a0.y, f0.y, b0.y);
    r0.z = fmaf(a0.z, f1.x, b0.z); r0.w = fmaf(a0.w, f1.y, b0.w);
    r1.x = fmaf(a1.x, f2.x, b1.x); r1.y = fmaf(a1.y, f2.y, b1.y);
    r1.z = fmaf(a1.z, f3.x, b1.z); r1.w = fmaf(a1.w, f3.y, b1.w);
    ((float4*)out)[2 * i]     = r0;
    ((float4*)out)[2 * i + 1] = r1;
}

extern "C" void kernel_launch(void* const* d_in, const int* in_sizes, int n_in,
                              void* d_out, int out_size) {
    (void)in_sizes; (void)n_in; (void)out_size;
    const float* x     = (const float*)d_in[0];
    const float* w     = (const float*)d_in[1];
    const float* gamma = (const float*)d_in[3];
    const float* beta  = (const float*)d_in[4];
    float* out = (float*)d_out;

    cudaFuncSetAttribute(gemm_kernel, cudaFuncAttributeMaxDynamicSharedMemorySize, GEMM_SMEM);

    cvt_x_kernel<<<16384, 256>>>(x);
    cvt_w_kernel<<<8192, 256>>>(w);
    gemm_kernel<<<dim3(B_DIM / TM, OUT_DIM / TN), 256, GEMM_SMEM>>>();
    coef_kernel<<<16, 256>>>(gamma, beta);
    norm_kernel<<<16384, 256>>>(out);
}

// round 8
// speedup vs baseline: 1.2076x; 1.0155x over previous
#include <cuda_runtime.h>
#include <cuda_fp16.h>
#include <cstdint>
#include <cstddef>

#define B_DIM   8192
#define IN_DIM  4096
#define OUT_DIM 4096

// static device scratch (runtime allocation forbidden)
__device__ __align__(16) __half g_x16[(size_t)B_DIM * IN_DIM];
__device__ __align__(16) __half g_w16[(size_t)OUT_DIM * IN_DIM];
__device__ __align__(16) __half g_o16[(size_t)B_DIM * OUT_DIM];
__device__ __align__(16) float  g_sum[OUT_DIM];
__device__ __align__(16) float  g_sqs[OUT_DIM];
__device__ __align__(16) float  g_cA[OUT_DIM];
__device__ __align__(16) float  g_cB[OUT_DIM];

// ---------------- GEMM config ----------------
#define TM 128
#define TN 128
#define TK 64
#define NSTAGE 3
#define KITERS (IN_DIM / TK)        // 64
#define A_STG (TM * 128)            // 16 KB
#define B_STG (TN * 128)            // 16 KB
#define STG_BYTES (A_STG + B_STG)   // 32 KB
#define GEMM_SMEM (NSTAGE * STG_BYTES)  // 96 KB -> 2 CTAs/SM

__device__ __forceinline__ uint32_t smem_u32(const void* p) {
    uint32_t r;
    asm("{ .reg .u64 t; cvta.to.shared.u64 t, %1; cvt.u32.u64 %0, t; }" : "=r"(r) : "l"(p));
    return r;
}
__device__ __forceinline__ uint32_t sw128(uint32_t o) { return o ^ ((o >> 3) & 0x70); }

#define CP_ASYNC16(dst, src) \
    asm volatile("cp.async.cg.shared.global [%0], [%1], 16;" :: "r"(dst), "l"(src) : "memory")

__device__ __forceinline__ void ldsm_x4(uint32_t* r, uint32_t addr) {
    asm volatile("ldmatrix.sync.aligned.m8n8.x4.shared.b16 {%0,%1,%2,%3}, [%4];"
                 : "=r"(r[0]), "=r"(r[1]), "=r"(r[2]), "=r"(r[3]) : "r"(addr));
}
__device__ __forceinline__ void mma16816(float* c, const uint32_t* a, const uint32_t* b) {
    asm volatile("mma.sync.aligned.m16n8k16.row.col.f32.f16.f16.f32 "
                 "{%0,%1,%2,%3}, {%4,%5,%6,%7}, {%8,%9}, {%0,%1,%2,%3};"
                 : "+f"(c[0]), "+f"(c[1]), "+f"(c[2]), "+f"(c[3])
                 : "r"(a[0]), "r"(a[1]), "r"(a[2]), "r"(a[3]), "r"(b[0]), "r"(b[1]));
}

// ---------------- conversion kernels ----------------
__global__ void cvt_x_kernel(const float* __restrict__ x) {
    size_t i = (size_t)blockIdx.x * blockDim.x + threadIdx.x;
    const float4* p = (const float4*)x;
    float4 a = p[2 * i], b = p[2 * i + 1];
    __half2 h0 = __floats2half2_rn(a.x, a.y), h1 = __floats2half2_rn(a.z, a.w);
    __half2 h2 = __floats2half2_rn(b.x, b.y), h3 = __floats2half2_rn(b.z, b.w);
    uint4 o;
    o.x = *(uint32_t*)&h0; o.y = *(uint32_t*)&h1;
    o.z = *(uint32_t*)&h2; o.w = *(uint32_t*)&h3;
    ((uint4*)g_x16)[i] = o;
}

__global__ void cvt_w_kernel(const float* __restrict__ w) {
    size_t i = (size_t)blockIdx.x * blockDim.x + threadIdx.x;
    if (i < OUT_DIM) { g_sum[i] = 0.f; g_sqs[i] = 0.f; }   // fused stats zeroing
    const float4* p = (const float4*)w;
    float4 a = p[2 * i], b = p[2 * i + 1];
    float s[8] = {a.x, a.y, a.z, a.w, b.x, b.y, b.z, b.w};
    __half h[8];
#pragma unroll
    for (int k = 0; k < 8; k++) {
        float v = s[k];
        h[k] = __float2half_rn((v > 0.f) ? 1.f : ((v < 0.f) ? -1.f : 0.f));
    }
    uint4 o;
    o.x = *(uint32_t*)&h[0]; o.y = *(uint32_t*)&h[2];
    o.z = *(uint32_t*)&h[4]; o.w = *(uint32_t*)&h[6];
    ((uint4*)g_w16)[i] = o;
}

// ------- GEMM: 128x128 CTA, 8 warps (64x32 warp tiles), 2 CTAs/SM -----------
__global__ void __launch_bounds__(256, 2) gemm_kernel() {
    extern __shared__ char smem[];
    uint32_t sb = smem_u32(smem);
    const int tid = threadIdx.x;
    const int wid = tid >> 5, lid = tid & 31;
    const int wm = wid >> 2, wn = wid & 3;        // 2 x 4 warp grid -> 64x32 tiles
    const int m0 = blockIdx.x * TM, n0 = blockIdx.y * TN;

    const __half* gA = g_x16 + (size_t)m0 * IN_DIM;
    const __half* gB = g_w16 + (size_t)n0 * IN_DIM;

    const int ldr = tid >> 3, ldq = tid & 7;

    // 8 chunks/thread: j<4 -> A rows, j>=4 -> B rows (each 128 rows)
    auto issue_chunk = [&](int c, int j) {
        uint32_t base = sb + (uint32_t)(c % NSTAGE) * STG_BYTES;
        if (j < 4) {
            int r = ldr + j * 32;
            CP_ASYNC16(base + sw128((uint32_t)(r * 128 + ldq * 16)),
                       gA + (size_t)c * TK + (size_t)r * IN_DIM + ldq * 8);
        } else {
            int r = ldr + (j - 4) * 32;
            CP_ASYNC16(base + A_STG + sw128((uint32_t)(r * 128 + ldq * 16)),
                       gB + (size_t)c * TK + (size_t)r * IN_DIM + ldq * 8);
        }
    };

#pragma unroll
    for (int c = 0; c < 2; c++) {
#pragma unroll
        for (int j = 0; j < 8; j++) issue_chunk(c, j);
        asm volatile("cp.async.commit_group;" ::: "memory");
    }

    float acc[4][4][4];
#pragma unroll
    for (int mi = 0; mi < 4; mi++)
#pragma unroll
        for (int ni = 0; ni < 4; ni++)
#pragma unroll
            for (int q = 0; q < 4; q++) acc[mi][ni][q] = 0.f;

    const uint32_t a_row_l = (uint32_t)(wm * 64 + (lid & 15));
    const uint32_t a_col_l = (uint32_t)((lid >> 4) * 16);
    const uint32_t b_row_l = (uint32_t)(wn * 32 + (lid & 7) + ((lid >> 4) << 3));
    const uint32_t b_col_l = (uint32_t)(((lid >> 3) & 1) * 16);

    uint32_t aF[4][4], bF[2][4];   // single-buffered fragments

    for (int c = 0; c < KITERS; c++) {
        uint32_t abase = sb + (uint32_t)(c % NSTAGE) * STG_BYTES;
        uint32_t bbase = abase + A_STG;
        const bool pf = (c + 2 < KITERS);

        asm volatile("cp.async.wait_group 1;" ::: "memory");
        __syncthreads();

#pragma unroll
        for (int s = 0; s < 4; s++) {
#pragma unroll
            for (int mi = 0; mi < 4; mi++)
                ldsm_x4(aF[mi], abase + sw128((a_row_l + mi * 16) * 128 + a_col_l + s * 32));
#pragma unroll
            for (int nb = 0; nb < 2; nb++)
                ldsm_x4(bF[nb], bbase + sw128((b_row_l + nb * 16) * 128 + b_col_l + s * 32));
            if (pf) { issue_chunk(c + 2, 2 * s); issue_chunk(c + 2, 2 * s + 1); }
#pragma unroll
            for (int mi = 0; mi < 4; mi++)
#pragma unroll
                for (int nb = 0; nb < 2; nb++) {
                    mma16816(acc[mi][2 * nb],     aF[mi], &bF[nb][0]);
                    mma16816(acc[mi][2 * nb + 1], aF[mi], &bF[nb][2]);
                }
        }
        asm volatile("cp.async.commit_group;" ::: "memory");
    }

    // ---- epilogue: fp16 store + fused column stats (fp32) ----
    const int trow = lid >> 2, tcol = (lid & 3) * 2;
#pragma unroll
    for (int mi = 0; mi < 4; mi++) {
#pragma unroll
        for (int ni = 0; ni < 4; ni++) {
            int row = m0 + wm * 64 + mi * 16 + trow;
            int col = n0 + wn * 32 + ni * 8 + tcol;
            __half* p = g_o16 + (size_t)row * OUT_DIM + col;
            *(__half2*)p = __floats2half2_rn(acc[mi][ni][0], acc[mi][ni][1]);
            *(__half2*)(p + 8 * OUT_DIM) = __floats2half2_rn(acc[mi][ni][2], acc[mi][ni][3]);
        }
    }
#pragma unroll
    for (int ni = 0; ni < 4; ni++) {
        float s0 = 0.f, s1 = 0.f, q0 = 0.f, q1 = 0.f;
#pragma unroll
        for (int mi = 0; mi < 4; mi++) {
            float v0 = acc[mi][ni][0], v1 = acc[mi][ni][1];
            float v2 = acc[mi][ni][2], v3 = acc[mi][ni][3];
            s0 += v0 + v2; s1 += v1 + v3;
            q0 += v0 * v0 + v2 * v2; q1 += v1 * v1 + v3 * v3;
        }
#pragma unroll
        for (int off = 4; off < 32; off <<= 1) {
            s0 += __shfl_xor_sync(0xffffffffu, s0, off);
            s1 += __shfl_xor_sync(0xffffffffu, s1, off);
            q0 += __shfl_xor_sync(0xffffffffu, q0, off);
            q1 += __shfl_xor_sync(0xffffffffu, q1, off);
        }
        if (trow == 0) {
            int col = n0 + wn * 32 + ni * 8 + tcol;
            atomicAdd(&g_sum[col], s0);
            atomicAdd(&g_sum[col + 1], s1);
            atomicAdd(&g_sqs[col], q0);
            atomicAdd(&g_sqs[col + 1], q1);
        }
    }
}

// ---------------- BatchNorm tail ----------------
__global__ void coef_kernel(const float* __restrict__ gamma, const float* __restrict__ beta) {
    int c = blockIdx.x * 256 + threadIdx.x;
    float mu = g_sum[c] * (1.f / B_DIM);
    float var = g_sqs[c] * (1.f / B_DIM) - mu * mu;
    float a = gamma[c] * rsqrtf(var + 1e-5f);
    g_cA[c] = a;
    g_cB[c] = beta[c] - a * mu;
}

__global__ void norm_kernel(float* __restrict__ out) {
    size_t i = (size_t)blockIdx.x * blockDim.x + threadIdx.x;  // one 8-half group
    int col = (int)((i * 8) & (OUT_DIM - 1));
    uint4 v = ((const uint4*)g_o16)[i];
    float4 a0 = *(const float4*)&g_cA[col];
    float4 a1 = *(const float4*)&g_cA[col + 4];
    float4 b0 = *(const float4*)&g_cB[col];
    float4 b1 = *(const float4*)&g_cB[col + 4];
    float2 f0 = __half22float2(*(__half2*)&v.x);
    float2 f1 = __half22float2(*(__half2*)&v.y);
    float2 f2 = __half22float2(*(__half2*)&v.z);
    float2 f3 = __half22float2(*(__half2*)&v.w);
    float4 r0, r1;
    r0.x = fmaf(a0.x, f0.x, b0.x); r0.y = fmaf(a0.y, f0.y, b0.y);
    r0.z = fmaf(a0.z, f1.x, b0.z); r0.w = fmaf(a0.w, f1.y, b0.w);
    r1.x = fmaf(a1.x, f2.x, b1.x); r1.y = fmaf(a1.y, f2.y, b1.y);
    r1.z = fmaf(a1.z, f3.x, b1.z); r1.w = fmaf(a1.w, f3.y, b1.w);
    ((float4*)out)[2 * i]     = r0;
    ((float4*)out)[2 * i + 1] = r1;
}

extern "C" void kernel_launch(void* const* d_in, const int* in_sizes, int n_in,
                              void* d_out, int out_size) {
    (void)in_sizes; (void)n_in; (void)out_size;
    const float* x     = (const float*)d_in[0];
    const float* w     = (const float*)d_in[1];
    const float* gamma = (const float*)d_in[3];
    const float* beta  = (const float*)d_in[4];
    float* out = (float*)d_out;

    cudaFuncSetAttribute(gemm_kernel, cudaFuncAttributeMaxDynamicSharedMemorySize, GEMM_SMEM);

    cvt_x_kernel<<<16384, 256>>>(x);
    cvt_w_kernel<<<8192, 256>>>(w);
    gemm_kernel<<<dim3(B_DIM / TM, OUT_DIM / TN), 256, GEMM_SMEM>>>();
    coef_kernel<<<16, 256>>>(gamma, beta);
    norm_kernel<<<16384, 256>>>(out);
}